// round 2
// baseline (speedup 1.0000x reference)
#include <cuda_runtime.h>
#include <cstdint>

#define BATCH 4
#define SEQ   2048
#define EMB   1024
#define HEADS 16
#define HDIM  64
#define MROWS (BATCH*SEQ)   // 8192

// Scratch (no allocations allowed) — 4 x 32 MB fp32
__device__ float g_q[BATCH*HEADS*SEQ*HDIM];
__device__ float g_k[BATCH*HEADS*SEQ*HDIM];
__device__ float g_v[BATCH*HEADS*SEQ*HDIM];
__device__ float g_ao[BATCH*SEQ*EMB];

// ---------------------------------------------------------------------------
// SGEMM: C = A[M,K] @ B[K,N] + bias[N]
// headsplit=1: store C[m][n] at q/k/v layout [b][h][s][d] (b=m/S, s=m%S, h=n/D, d=n%D)
// Tiling: 128x128x16, 256 threads, 8x8 micro-tile per thread.
// ---------------------------------------------------------------------------
__global__ __launch_bounds__(256)
void sgemm_kernel(const float* __restrict__ A, const float* __restrict__ Bm,
                  const float* __restrict__ bias, float* __restrict__ C,
                  int M, int N, int K, int headsplit)
{
    __shared__ __align__(16) float As[128][17];   // [m][k], +1 pad
    __shared__ __align__(16) float Bs[16][128];   // [k][n]

    const int tid = threadIdx.x;
    const int tx  = tid & 15;        // 0..15  -> col group
    const int ty  = tid >> 4;        // 0..15  -> row group
    const int row0 = blockIdx.y * 128;
    const int col0 = blockIdx.x * 128;

    float acc[8][8];
#pragma unroll
    for (int i = 0; i < 8; i++)
#pragma unroll
        for (int j = 0; j < 8; j++) acc[i][j] = 0.f;

    const int ar  = tid >> 2;          // 0..63
    const int ac4 = (tid & 3) * 4;     // 0,4,8,12
    const int bkr = tid >> 5;          // 0..7
    const int bc4 = (tid & 31) * 4;    // 0..124

    for (int k0 = 0; k0 < K; k0 += 16) {
        // load A tile: 128x16
        {
            const float4 a0 = *(const float4*)&A[(size_t)(row0 + ar) * K + k0 + ac4];
            As[ar][ac4+0] = a0.x; As[ar][ac4+1] = a0.y; As[ar][ac4+2] = a0.z; As[ar][ac4+3] = a0.w;
            const float4 a1 = *(const float4*)&A[(size_t)(row0 + ar + 64) * K + k0 + ac4];
            As[ar+64][ac4+0] = a1.x; As[ar+64][ac4+1] = a1.y; As[ar+64][ac4+2] = a1.z; As[ar+64][ac4+3] = a1.w;
        }
        // load B tile: 16x128
        {
            *(float4*)&Bs[bkr    ][bc4] = *(const float4*)&Bm[(size_t)(k0 + bkr    ) * N + col0 + bc4];
            *(float4*)&Bs[bkr + 8][bc4] = *(const float4*)&Bm[(size_t)(k0 + bkr + 8) * N + col0 + bc4];
        }
        __syncthreads();

#pragma unroll
        for (int k = 0; k < 16; k++) {
            float a[8], b[8];
#pragma unroll
            for (int i = 0; i < 8; i++) a[i] = As[ty*8 + i][k];
            const float4 b0 = *(const float4*)&Bs[k][tx*8];
            const float4 b1 = *(const float4*)&Bs[k][tx*8 + 4];
            b[0]=b0.x; b[1]=b0.y; b[2]=b0.z; b[3]=b0.w;
            b[4]=b1.x; b[5]=b1.y; b[6]=b1.z; b[7]=b1.w;
#pragma unroll
            for (int i = 0; i < 8; i++)
#pragma unroll
                for (int j = 0; j < 8; j++)
                    acc[i][j] = fmaf(a[i], b[j], acc[i][j]);
        }
        __syncthreads();
    }

    // epilogue
#pragma unroll
    for (int i = 0; i < 8; i++) {
        const int m = row0 + ty*8 + i;
#pragma unroll
        for (int j = 0; j < 8; j++) {
            const int n = col0 + tx*8 + j;
            const float v = acc[i][j] + bias[n];
            if (headsplit) {
                const int b = m / SEQ, s = m % SEQ;
                const int h = n / HDIM, d = n % HDIM;
                C[(((size_t)(b*HEADS + h))*SEQ + s)*HDIM + d] = v;
            } else {
                C[(size_t)m * N + n] = v;
            }
        }
    }
}

// ---------------------------------------------------------------------------
// Causal flash attention, fp32. One warp per query row, 8 rows per block.
// K chunk (32 keys) staged transposed in SMEM (Ks[d][j]), V row-major.
// Writes O in [b][s][h*D+d] layout (ready for output projection).
// ---------------------------------------------------------------------------
__global__ __launch_bounds__(256)
void attn_kernel(const float* __restrict__ Q, const float* __restrict__ Kg,
                 const float* __restrict__ Vg, float* __restrict__ O)
{
    __shared__ __align__(16) float Ks[64][33];   // [d][j], pad j
    __shared__ __align__(16) float Vs[32][64];   // [j][d]

    const int bh   = blockIdx.y;            // b*H + h
    const int warp = threadIdx.x >> 5;
    const int lane = threadIdx.x & 31;
    const int s    = blockIdx.x * 8 + warp;
    const int s_hi = blockIdx.x * 8 + 7;

    const float* qrow  = Q + ((size_t)bh * SEQ + s) * HDIM;
    const float* Kbase = Kg + (size_t)bh * SEQ * HDIM;
    const float* Vbase = Vg + (size_t)bh * SEQ * HDIM;

    float q[64];
#pragma unroll
    for (int d = 0; d < 64; d += 4) {
        const float4 qv = *(const float4*)&qrow[d];
        q[d+0] = qv.x * 0.125f; q[d+1] = qv.y * 0.125f;
        q[d+2] = qv.z * 0.125f; q[d+3] = qv.w * 0.125f;
    }

    float m = -INFINITY, l = 0.f, o0 = 0.f, o1 = 0.f;
    const int nch = (s_hi >> 5) + 1;

    const int lj  = threadIdx.x >> 3;        // 0..31 : key index in chunk
    const int ld0 = (threadIdx.x & 7) * 8;   // 0..56 : dim offset

    for (int c = 0; c < nch; c++) {
        // cooperative load of 32 keys (K transposed, V row-major)
        {
            const float* kr = Kbase + (size_t)(c*32 + lj) * HDIM + ld0;
            const float4 k0 = *(const float4*)kr;
            const float4 k1 = *(const float4*)(kr + 4);
            Ks[ld0+0][lj] = k0.x; Ks[ld0+1][lj] = k0.y; Ks[ld0+2][lj] = k0.z; Ks[ld0+3][lj] = k0.w;
            Ks[ld0+4][lj] = k1.x; Ks[ld0+5][lj] = k1.y; Ks[ld0+6][lj] = k1.z; Ks[ld0+7][lj] = k1.w;
            const float* vr = Vbase + (size_t)(c*32 + lj) * HDIM + ld0;
            *(float4*)&Vs[lj][ld0]     = *(const float4*)vr;
            *(float4*)&Vs[lj][ld0 + 4] = *(const float4*)(vr + 4);
        }
        __syncthreads();

        if (c * 32 <= s) {
            const int key = c * 32 + lane;
            float sc = -INFINITY;
            if (key <= s) {
                sc = 0.f;
#pragma unroll
                for (int d = 0; d < 64; d++)
                    sc = fmaf(q[d], Ks[d][lane], sc);
            }
            // warp max
            float mx = sc;
#pragma unroll
            for (int off = 16; off > 0; off >>= 1)
                mx = fmaxf(mx, __shfl_xor_sync(0xffffffffu, mx, off));
            const float mnew = fmaxf(m, mx);
            const float p    = __expf(sc - mnew);   // exp(-inf)=0 for masked
            const float corr = __expf(m - mnew);    // first chunk: 0
            float ps = p;
#pragma unroll
            for (int off = 16; off > 0; off >>= 1)
                ps += __shfl_xor_sync(0xffffffffu, ps, off);
            l = l * corr + ps;
            o0 *= corr; o1 *= corr;
#pragma unroll
            for (int j = 0; j < 32; j++) {
                const float pj = __shfl_sync(0xffffffffu, p, j);
                o0 = fmaf(pj, Vs[j][lane],      o0);
                o1 = fmaf(pj, Vs[j][lane + 32], o1);
            }
            m = mnew;
        }
        __syncthreads();
    }

    const float inv = 1.f / l;
    const int b = bh / HEADS, h = bh % HEADS;
    float* orow = O + ((size_t)(b * SEQ + s)) * EMB + h * HDIM;
    orow[lane]      = o0 * inv;
    orow[lane + 32] = o1 * inv;
}

// ---------------------------------------------------------------------------
extern "C" void kernel_launch(void* const* d_in, const int* in_sizes, int n_in,
                              void* d_out, int out_size)
{
    const float* x  = (const float*)d_in[0];
    const float* Wq = (const float*)d_in[1];
    const float* bq = (const float*)d_in[2];
    const float* Wk = (const float*)d_in[3];
    const float* bk = (const float*)d_in[4];
    const float* Wv = (const float*)d_in[5];
    const float* bv = (const float*)d_in[6];
    const float* Wo = (const float*)d_in[7];
    const float* bo = (const float*)d_in[8];
    float* out = (float*)d_out;

    float *q_ptr, *k_ptr, *v_ptr, *ao_ptr;
    cudaGetSymbolAddress((void**)&q_ptr,  g_q);
    cudaGetSymbolAddress((void**)&k_ptr,  g_k);
    cudaGetSymbolAddress((void**)&v_ptr,  g_v);
    cudaGetSymbolAddress((void**)&ao_ptr, g_ao);

    dim3 gblk(256);
    dim3 ggrid(EMB / 128, MROWS / 128);   // (8, 64)

    sgemm_kernel<<<ggrid, gblk>>>(x, Wq, bq, q_ptr, MROWS, EMB, EMB, 1);
    sgemm_kernel<<<ggrid, gblk>>>(x, Wk, bk, k_ptr, MROWS, EMB, EMB, 1);
    sgemm_kernel<<<ggrid, gblk>>>(x, Wv, bv, v_ptr, MROWS, EMB, EMB, 1);

    dim3 agrid(SEQ / 8, BATCH * HEADS);   // (256, 64)
    attn_kernel<<<agrid, 256>>>(q_ptr, k_ptr, v_ptr, ao_ptr);

    sgemm_kernel<<<ggrid, gblk>>>(ao_ptr, Wo, bo, out, MROWS, EMB, EMB, 0);
}

// round 3
// speedup vs baseline: 1.7646x; 1.7646x over previous
#include <cuda_runtime.h>
#include <cstdint>
#include <cmath>

#define BATCH 4
#define SEQ   2048
#define EMB   1024
#define HEADS 16
#define HDIM  64
#define MROWS (BATCH*SEQ)   // 8192

// Scratch (no allocations allowed)
__device__ float g_q[BATCH*HEADS*SEQ*HDIM];
__device__ float g_k[BATCH*HEADS*SEQ*HDIM];
__device__ float g_v[BATCH*HEADS*SEQ*HDIM];
__device__ float g_ao[BATCH*SEQ*EMB];

// ---------------------------------------------------------------------------
// helpers
// ---------------------------------------------------------------------------
__device__ __forceinline__ uint32_t tf32_rna(float x) {
    uint32_t r;
    asm("cvt.rna.tf32.f32 %0, %1;" : "=r"(r) : "f"(x));
    return r;
}
__device__ __forceinline__ void tf32_split(float x, uint32_t& hi, uint32_t& lo) {
    hi = tf32_rna(x);
    lo = tf32_rna(x - __uint_as_float(hi));
}
__device__ __forceinline__ void mma_tf32(float* c, const uint32_t* a, const uint32_t* b) {
    asm volatile(
        "mma.sync.aligned.m16n8k8.row.col.f32.tf32.tf32.f32 "
        "{%0,%1,%2,%3}, {%4,%5,%6,%7}, {%8,%9}, {%0,%1,%2,%3};"
        : "+f"(c[0]), "+f"(c[1]), "+f"(c[2]), "+f"(c[3])
        : "r"(a[0]), "r"(a[1]), "r"(a[2]), "r"(a[3]), "r"(b[0]), "r"(b[1]));
}

// ---------------------------------------------------------------------------
// 3xTF32 GEMM: C = A[M,K] @ B[K,N] + bias.  Tile 128x128x16, 256 thr, 8 warps.
// warp layout 4(m) x 2(n): each warp 32 rows x 64 cols.
// ---------------------------------------------------------------------------
__global__ __launch_bounds__(256)
void gemm_tf32(const float* __restrict__ A, const float* __restrict__ Bm,
               const float* __restrict__ bias, float* __restrict__ C,
               int M, int N, int K, int headsplit)
{
    __shared__ __align__(16) float As[128][20];
    __shared__ __align__(16) float Bs[16][136];

    const int tid  = threadIdx.x;
    const int wid  = tid >> 5;
    const int lane = tid & 31;
    const int gid  = lane >> 2;   // 0..7
    const int tig  = lane & 3;    // 0..3
    const int wm   = wid >> 1;    // 0..3
    const int wn   = wid & 1;     // 0..1
    const int row0 = blockIdx.y * 128;
    const int col0 = blockIdx.x * 128;

    float c[2][8][4];
#pragma unroll
    for (int mt = 0; mt < 2; mt++)
#pragma unroll
        for (int nt = 0; nt < 8; nt++)
#pragma unroll
            for (int i = 0; i < 4; i++) c[mt][nt][i] = 0.f;

    const int ar = tid >> 1, ac = (tid & 1) * 8;
    const int br = tid >> 4, bc = (tid & 15) * 8;

    const float* Abase = A + (size_t)(row0 + ar) * K + ac;
    const float* Bbase = Bm + (size_t)br * N + col0 + bc;

    float4 aR0 = *(const float4*)(Abase);
    float4 aR1 = *(const float4*)(Abase + 4);
    float4 bR0 = *(const float4*)(Bbase);
    float4 bR1 = *(const float4*)(Bbase + 4);

    for (int k0 = 0; k0 < K; k0 += 16) {
        *(float4*)&As[ar][ac]     = aR0;
        *(float4*)&As[ar][ac + 4] = aR1;
        *(float4*)&Bs[br][bc]     = bR0;
        *(float4*)&Bs[br][bc + 4] = bR1;
        __syncthreads();

        if (k0 + 16 < K) {
            aR0 = *(const float4*)(Abase + k0 + 16);
            aR1 = *(const float4*)(Abase + k0 + 20);
            bR0 = *(const float4*)(Bbase + (size_t)(k0 + 16) * N);
            bR1 = *(const float4*)(Bbase + (size_t)(k0 + 16) * N + 4);
        }

#pragma unroll
        for (int ks = 0; ks < 2; ks++) {
            uint32_t ahi[2][4], alo[2][4];
#pragma unroll
            for (int mt = 0; mt < 2; mt++) {
                const int m0 = wm * 32 + mt * 16;
                float x0 = As[m0 + gid    ][ks * 8 + tig];
                float x1 = As[m0 + gid + 8][ks * 8 + tig];
                float x2 = As[m0 + gid    ][ks * 8 + tig + 4];
                float x3 = As[m0 + gid + 8][ks * 8 + tig + 4];
                tf32_split(x0, ahi[mt][0], alo[mt][0]);
                tf32_split(x1, ahi[mt][1], alo[mt][1]);
                tf32_split(x2, ahi[mt][2], alo[mt][2]);
                tf32_split(x3, ahi[mt][3], alo[mt][3]);
            }
#pragma unroll
            for (int nt = 0; nt < 8; nt++) {
                const int n0 = wn * 64 + nt * 8;
                float y0 = Bs[ks * 8 + tig    ][n0 + gid];
                float y1 = Bs[ks * 8 + tig + 4][n0 + gid];
                uint32_t bhi[2], blo[2];
                tf32_split(y0, bhi[0], blo[0]);
                tf32_split(y1, bhi[1], blo[1]);
#pragma unroll
                for (int mt = 0; mt < 2; mt++) {
                    mma_tf32(c[mt][nt], ahi[mt], bhi);
                    mma_tf32(c[mt][nt], alo[mt], bhi);
                    mma_tf32(c[mt][nt], ahi[mt], blo);
                }
            }
        }
        __syncthreads();
    }

    // epilogue
#pragma unroll
    for (int mt = 0; mt < 2; mt++) {
        const int m_lo = row0 + wm * 32 + mt * 16 + gid;
        const int m_hi = m_lo + 8;
#pragma unroll
        for (int nt = 0; nt < 8; nt++) {
            const int n = col0 + wn * 64 + nt * 8 + 2 * tig;
            const float b0 = bias[n], b1 = bias[n + 1];
            float v00 = c[mt][nt][0] + b0, v01 = c[mt][nt][1] + b1;
            float v10 = c[mt][nt][2] + b0, v11 = c[mt][nt][3] + b1;
            if (headsplit) {
                const int b_lo = m_lo / SEQ, s_lo = m_lo % SEQ;
                const int b_hi = m_hi / SEQ, s_hi = m_hi % SEQ;
                const int h = n / HDIM, d = n % HDIM;
                C[(((size_t)(b_lo*HEADS + h))*SEQ + s_lo)*HDIM + d    ] = v00;
                C[(((size_t)(b_lo*HEADS + h))*SEQ + s_lo)*HDIM + d + 1] = v01;
                C[(((size_t)(b_hi*HEADS + h))*SEQ + s_hi)*HDIM + d    ] = v10;
                C[(((size_t)(b_hi*HEADS + h))*SEQ + s_hi)*HDIM + d + 1] = v11;
            } else {
                C[(size_t)m_lo * N + n    ] = v00;
                C[(size_t)m_lo * N + n + 1] = v01;
                C[(size_t)m_hi * N + n    ] = v10;
                C[(size_t)m_hi * N + n + 1] = v11;
            }
        }
    }
}

// ---------------------------------------------------------------------------
// Causal flash attention with 3xTF32 mma.
// Block: 64 q-rows of one (b,h); 4 warps, warp w owns rows [w*16, w*16+16).
// Key chunks of 32.
// ---------------------------------------------------------------------------
__global__ __launch_bounds__(128)
void attn_tf32(const float* __restrict__ Q, const float* __restrict__ Kg,
               const float* __restrict__ Vg, float* __restrict__ O)
{
    __shared__ __align__(16) float Qs[64][68];
    __shared__ __align__(16) float Ks[32][68];
    __shared__ __align__(16) float Vs[32][72];
    __shared__ float Ss[64][36];
    __shared__ float mrow[64], lrow[64], srow[64];

    const int bh  = blockIdx.y;
    const int qt  = blockIdx.x;
    const int tid = threadIdx.x;
    const int wid = tid >> 5;
    const int lane = tid & 31;
    const int gid = lane >> 2;
    const int tig = lane & 3;
    const int m0  = wid * 16;

    const float* Qbase = Q + ((size_t)bh * SEQ + qt * 64) * HDIM;
    const float* Kbase = Kg + (size_t)bh * SEQ * HDIM;
    const float* Vbase = Vg + (size_t)bh * SEQ * HDIM;

    // stage Q tile (64x64)
    {
        const int qr = tid >> 1, qc = (tid & 1) * 32;
#pragma unroll
        for (int i = 0; i < 8; i++)
            *(float4*)&Qs[qr][qc + i * 4] = *(const float4*)(Qbase + (size_t)qr * HDIM + qc + i * 4);
    }
    if (tid < 64) { mrow[tid] = -INFINITY; lrow[tid] = 0.f; }
    __syncthreads();

    // Q fragments (scaled by 1/sqrt(D) = 0.125), hi/lo split, in registers
    uint32_t qhi[8][4], qlo[8][4];
#pragma unroll
    for (int ks = 0; ks < 8; ks++) {
        float x0 = Qs[m0 + gid    ][ks * 8 + tig]     * 0.125f;
        float x1 = Qs[m0 + gid + 8][ks * 8 + tig]     * 0.125f;
        float x2 = Qs[m0 + gid    ][ks * 8 + tig + 4] * 0.125f;
        float x3 = Qs[m0 + gid + 8][ks * 8 + tig + 4] * 0.125f;
        tf32_split(x0, qhi[ks][0], qlo[ks][0]);
        tf32_split(x1, qhi[ks][1], qlo[ks][1]);
        tf32_split(x2, qhi[ks][2], qlo[ks][2]);
        tf32_split(x3, qhi[ks][3], qlo[ks][3]);
    }

    float o[8][4];
#pragma unroll
    for (int nt = 0; nt < 8; nt++)
#pragma unroll
        for (int i = 0; i < 4; i++) o[nt][i] = 0.f;

    const int cmax = 2 * qt + 1;   // chunks of 32 keys
    for (int ch = 0; ch <= cmax; ch++) {
        // stage K,V chunk (32x64 each)
        {
            const int kr = tid >> 2, kc = (tid & 3) * 16;
            const float* kp = Kbase + (size_t)(ch * 32 + kr) * HDIM + kc;
            const float* vp = Vbase + (size_t)(ch * 32 + kr) * HDIM + kc;
#pragma unroll
            for (int i = 0; i < 4; i++) {
                *(float4*)&Ks[kr][kc + i * 4] = *(const float4*)(kp + i * 4);
                *(float4*)&Vs[kr][kc + i * 4] = *(const float4*)(vp + i * 4);
            }
        }
        __syncthreads();

        // S = Q K^T (16x32 per warp)
        float s[4][4];
#pragma unroll
        for (int nt = 0; nt < 4; nt++)
#pragma unroll
            for (int i = 0; i < 4; i++) s[nt][i] = 0.f;
#pragma unroll
        for (int ks = 0; ks < 8; ks++) {
#pragma unroll
            for (int nt = 0; nt < 4; nt++) {
                float y0 = Ks[nt * 8 + gid][ks * 8 + tig];
                float y1 = Ks[nt * 8 + gid][ks * 8 + tig + 4];
                uint32_t bhi[2], blo[2];
                tf32_split(y0, bhi[0], blo[0]);
                tf32_split(y1, bhi[1], blo[1]);
                mma_tf32(s[nt], qhi[ks], bhi);
                mma_tf32(s[nt], qlo[ks], bhi);
                mma_tf32(s[nt], qhi[ks], blo);
            }
        }
        // write S to SMEM
#pragma unroll
        for (int nt = 0; nt < 4; nt++) {
            const int cc = nt * 8 + 2 * tig;
            Ss[m0 + gid    ][cc]     = s[nt][0];
            Ss[m0 + gid    ][cc + 1] = s[nt][1];
            Ss[m0 + gid + 8][cc]     = s[nt][2];
            Ss[m0 + gid + 8][cc + 1] = s[nt][3];
        }
        __syncthreads();

        // online softmax: warp handles its 16 rows serially, lanes over 32 keys
#pragma unroll 1
        for (int i = 0; i < 16; i++) {
            const int r = m0 + i;
            const int qrow = qt * 64 + r;
            const int key  = ch * 32 + lane;
            float sc = (key <= qrow) ? Ss[r][lane] : -INFINITY;
            float mx = sc;
#pragma unroll
            for (int off = 16; off > 0; off >>= 1)
                mx = fmaxf(mx, __shfl_xor_sync(0xffffffffu, mx, off));
            const float mold = mrow[r];
            const float mnew = fmaxf(mold, mx);
            const float p = __expf(sc - mnew);
            float ps = p;
#pragma unroll
            for (int off = 16; off > 0; off >>= 1)
                ps += __shfl_xor_sync(0xffffffffu, ps, off);
            if (lane == 0) {
                const float corr = __expf(mold - mnew);
                lrow[r] = lrow[r] * corr + ps;
                srow[r] = corr;
                mrow[r] = mnew;
            }
            Ss[r][lane] = p;
        }
        __syncthreads();

        // rescale O, then O += P V
        {
            const float s0 = srow[m0 + gid];
            const float s1 = srow[m0 + 8 + gid];
#pragma unroll
            for (int nt = 0; nt < 8; nt++) {
                o[nt][0] *= s0; o[nt][1] *= s0;
                o[nt][2] *= s1; o[nt][3] *= s1;
            }
        }
#pragma unroll
        for (int ks = 0; ks < 4; ks++) {
            uint32_t phi[4], plo[4];
            {
                float x0 = Ss[m0 + gid    ][ks * 8 + tig];
                float x1 = Ss[m0 + gid + 8][ks * 8 + tig];
                float x2 = Ss[m0 + gid    ][ks * 8 + tig + 4];
                float x3 = Ss[m0 + gid + 8][ks * 8 + tig + 4];
                tf32_split(x0, phi[0], plo[0]);
                tf32_split(x1, phi[1], plo[1]);
                tf32_split(x2, phi[2], plo[2]);
                tf32_split(x3, phi[3], plo[3]);
            }
#pragma unroll
            for (int nt = 0; nt < 8; nt++) {
                float y0 = Vs[ks * 8 + tig    ][nt * 8 + gid];
                float y1 = Vs[ks * 8 + tig + 4][nt * 8 + gid];
                uint32_t vhi[2], vlo[2];
                tf32_split(y0, vhi[0], vlo[0]);
                tf32_split(y1, vhi[1], vlo[1]);
                mma_tf32(o[nt], phi, vhi);
                mma_tf32(o[nt], plo, vhi);
                mma_tf32(o[nt], phi, vlo);
            }
        }
        __syncthreads();
    }

    // epilogue: normalize and store to [b][s][h*64+d]
    const float inv0 = 1.f / lrow[m0 + gid];
    const float inv1 = 1.f / lrow[m0 + 8 + gid];
    const int b = bh / HEADS, h = bh % HEADS;
    const int sg0 = qt * 64 + m0 + gid;
    float* orow0 = O + ((size_t)(b * SEQ + sg0    )) * EMB + h * HDIM;
    float* orow1 = O + ((size_t)(b * SEQ + sg0 + 8)) * EMB + h * HDIM;
#pragma unroll
    for (int nt = 0; nt < 8; nt++) {
        const int cc = nt * 8 + 2 * tig;
        orow0[cc]     = o[nt][0] * inv0;
        orow0[cc + 1] = o[nt][1] * inv0;
        orow1[cc]     = o[nt][2] * inv1;
        orow1[cc + 1] = o[nt][3] * inv1;
    }
}

// ---------------------------------------------------------------------------
extern "C" void kernel_launch(void* const* d_in, const int* in_sizes, int n_in,
                              void* d_out, int out_size)
{
    const float* x  = (const float*)d_in[0];
    const float* Wq = (const float*)d_in[1];
    const float* bq = (const float*)d_in[2];
    const float* Wk = (const float*)d_in[3];
    const float* bk = (const float*)d_in[4];
    const float* Wv = (const float*)d_in[5];
    const float* bv = (const float*)d_in[6];
    const float* Wo = (const float*)d_in[7];
    const float* bo = (const float*)d_in[8];
    float* out = (float*)d_out;

    float *q_ptr, *k_ptr, *v_ptr, *ao_ptr;
    cudaGetSymbolAddress((void**)&q_ptr,  g_q);
    cudaGetSymbolAddress((void**)&k_ptr,  g_k);
    cudaGetSymbolAddress((void**)&v_ptr,  g_v);
    cudaGetSymbolAddress((void**)&ao_ptr, g_ao);

    dim3 gblk(256);
    dim3 ggrid(EMB / 128, MROWS / 128);   // (8, 64)

    gemm_tf32<<<ggrid, gblk>>>(x, Wq, bq, q_ptr, MROWS, EMB, EMB, 1);
    gemm_tf32<<<ggrid, gblk>>>(x, Wk, bk, k_ptr, MROWS, EMB, EMB, 1);
    gemm_tf32<<<ggrid, gblk>>>(x, Wv, bv, v_ptr, MROWS, EMB, EMB, 1);

    dim3 agrid(SEQ / 64, BATCH * HEADS);  // (32, 64)
    attn_tf32<<<agrid, 128>>>(q_ptr, k_ptr, v_ptr, ao_ptr);

    gemm_tf32<<<ggrid, gblk>>>(ao_ptr, Wo, bo, out, MROWS, EMB, EMB, 0);
}